// round 2
// baseline (speedup 1.0000x reference)
#include <cuda_runtime.h>
#include <cstdint>

#define N_NODES 200000
#define D 64

// Scratch (allocation-free rule: __device__ globals)
__device__ float g_nbr[(size_t)N_NODES * D];   // 51.2 MB
__device__ float g_h1 [(size_t)N_NODES * D];   // 51.2 MB

// ---------------------------------------------------------------------------
// Zero the scatter buffer (float4 grid-stride)
// ---------------------------------------------------------------------------
__global__ void zero_kernel(float4* __restrict__ p, int n4) {
    int i = blockIdx.x * blockDim.x + threadIdx.x;
    int stride = gridDim.x * blockDim.x;
    float4 z = make_float4(0.f, 0.f, 0.f, 0.f);
    for (; i < n4; i += stride) p[i] = z;
}

// ---------------------------------------------------------------------------
// COO SpMM: out[rows[e]] += vals[e] * x[cols[e]]
// 16 lanes per edge (2 edges per warp); lane c owns float4 chunk c of the row.
// Edge scalars are loaded once by 2 lanes and broadcast via shfl.
// Gather: 256B coalesced per edge. Scatter: red.global.add.v4.f32 (no return).
// ---------------------------------------------------------------------------
__global__ void __launch_bounds__(256)
spmm_kernel(const int*   __restrict__ rows,
            const int*   __restrict__ cols,
            const float* __restrict__ vals,
            const float* __restrict__ x,
            float*       __restrict__ out,
            int E) {
    long long idx  = (long long)blockIdx.x * blockDim.x + threadIdx.x;
    int lane = threadIdx.x & 31;
    int half = lane >> 4;                 // which edge within the warp (0/1)
    int c    = lane & 15;                 // float4 chunk within the row

    long long warp_id = idx >> 5;
    long long e_ll    = warp_id * 2 + half;
    if (e_ll >= E) return;
    int e = (int)e_ll;

    // lanes 0 and 16 load the edge scalars for their half; broadcast to the half
    int r_l = 0, col_l = 0; float v_l = 0.f;
    if (c == 0) {
        r_l   = __ldg(rows + e);
        col_l = __ldg(cols + e);
        v_l   = __ldg(vals + e);
    }
    int src = half << 4;                  // lane 0 or 16
    int   r   = __shfl_sync(0xFFFFFFFFu, r_l,   src);
    int   col = __shfl_sync(0xFFFFFFFFu, col_l, src);
    float v   = __shfl_sync(0xFFFFFFFFu, v_l,   src);

    float4 xv = __ldg(((const float4*)x) + (long long)col * 16 + c);
    float4 m  = make_float4(xv.x * v, xv.y * v, xv.z * v, xv.w * v);

    float* addr = out + (long long)r * D + c * 4;
    asm volatile("red.global.add.v4.f32 [%0], {%1,%2,%3,%4};"
                 :: "l"(addr), "f"(m.x), "f"(m.y), "f"(m.z), "f"(m.w)
                 : "memory");
}

// ---------------------------------------------------------------------------
// Fused concat + GEMM + bias + ReLU:
//   out[n][j] = relu( b[j] + sum_k h[n][k]*W[k][j] + sum_k nbr[n][k]*W[64+k][j] )
// Block: 256 threads, 128 rows. W (128x64) staged in smem; X rows staged with
// stride-65 padding (bank-conflict-free scalar broadcasts). Each thread owns
// 2 rows x 16 columns (8 float4 accumulators) -> 4096 FMA / 512 LDS.128.
// ---------------------------------------------------------------------------
#define DB_ROWS 128
#define DB_THREADS 256
#define XPITCH 65
#define DENSE_SMEM ((128*64 + 2*DB_ROWS*XPITCH) * sizeof(float))

__global__ void __launch_bounds__(DB_THREADS)
dense_kernel(const float* __restrict__ Xh,
             const float* __restrict__ Xn,
             const float* __restrict__ W,   // [128][64] row-major
             const float* __restrict__ b,   // [64]
             float*       __restrict__ out, // [N][64]
             int N) {
    extern __shared__ float sm[];
    float*  Ws  = sm;                 // 128*64 floats
    float*  Xs  = sm + 128 * 64;      // [2][DB_ROWS][XPITCH]
    float4* Ws4 = (float4*)Ws;

    int tid  = threadIdx.x;
    int base = blockIdx.x * DB_ROWS;

    // Stage W (coalesced float4)
    const float4* Wg = (const float4*)W;
    for (int i = tid; i < 128 * 16; i += DB_THREADS) Ws4[i] = __ldg(Wg + i);

    // Stage X rows (h and nbr), padded pitch 65
    int nr = N - base; if (nr > DB_ROWS) nr = DB_ROWS;
    for (int i = tid; i < nr * D; i += DB_THREADS) {
        int r = i >> 6, c = i & 63;
        Xs[r * XPITCH + c]                    = __ldg(Xh + (size_t)(base + r) * D + c);
        Xs[DB_ROWS * XPITCH + r * XPITCH + c] = __ldg(Xn + (size_t)(base + r) * D + c);
    }
    __syncthreads();

    int q    = tid & 3;     // column quarter: j in [16q, 16q+16)
    int slot = tid >> 2;    // 0..63 ; rows slot and slot+64

    float4 a0[4], a1[4];
    #pragma unroll
    for (int v = 0; v < 4; v++) {
        float4 bv = __ldg(((const float4*)b) + q * 4 + v);
        a0[v] = bv; a1[v] = bv;
    }

    const float* xh0 = Xs + slot * XPITCH;
    const float* xh1 = Xs + (slot + 64) * XPITCH;
    const float* xn0 = Xs + DB_ROWS * XPITCH + slot * XPITCH;
    const float* xn1 = Xs + DB_ROWS * XPITCH + (slot + 64) * XPITCH;

    #pragma unroll 4
    for (int k = 0; k < 64; k++) {
        float h0 = xh0[k], h1 = xh1[k];
        float n0 = xn0[k], n1 = xn1[k];
        #pragma unroll
        for (int v = 0; v < 4; v++) {
            float4 wh = Ws4[k * 16 + q * 4 + v];
            float4 wn = Ws4[(64 + k) * 16 + q * 4 + v];
            a0[v].x += h0 * wh.x + n0 * wn.x;
            a0[v].y += h0 * wh.y + n0 * wn.y;
            a0[v].z += h0 * wh.z + n0 * wn.z;
            a0[v].w += h0 * wh.w + n0 * wn.w;
            a1[v].x += h1 * wh.x + n1 * wn.x;
            a1[v].y += h1 * wh.y + n1 * wn.y;
            a1[v].z += h1 * wh.z + n1 * wn.z;
            a1[v].w += h1 * wh.w + n1 * wn.w;
        }
    }

    float4* out4 = (float4*)out;
    int r0 = base + slot, r1 = base + slot + 64;
    if (r0 < N) {
        #pragma unroll
        for (int v = 0; v < 4; v++) {
            float4 t = a0[v];
            t.x = fmaxf(t.x, 0.f); t.y = fmaxf(t.y, 0.f);
            t.z = fmaxf(t.z, 0.f); t.w = fmaxf(t.w, 0.f);
            out4[(size_t)r0 * 16 + q * 4 + v] = t;
        }
    }
    if (r1 < N) {
        #pragma unroll
        for (int v = 0; v < 4; v++) {
            float4 t = a1[v];
            t.x = fmaxf(t.x, 0.f); t.y = fmaxf(t.y, 0.f);
            t.z = fmaxf(t.z, 0.f); t.w = fmaxf(t.w, 0.f);
            out4[(size_t)r1 * 16 + q * 4 + v] = t;
        }
    }
}

// ---------------------------------------------------------------------------
extern "C" void kernel_launch(void* const* d_in, const int* in_sizes, int n_in,
                              void* d_out, int out_size) {
    const int*   rows = (const int*)  d_in[0];
    const int*   cols = (const int*)  d_in[1];
    const float* vals = (const float*)d_in[2];
    const float* emb  = (const float*)d_in[3];
    const float* W1   = (const float*)d_in[4];
    const float* b1   = (const float*)d_in[5];
    const float* W2   = (const float*)d_in[6];
    const float* b2   = (const float*)d_in[7];
    float* out = (float*)d_out;

    int E = in_sizes[0];
    int N = in_sizes[3] / D;

    float *nbr, *h1;
    cudaGetSymbolAddress((void**)&nbr, g_nbr);
    cudaGetSymbolAddress((void**)&h1,  g_h1);

    cudaFuncSetAttribute(dense_kernel,
                         cudaFuncAttributeMaxDynamicSharedMemorySize,
                         (int)DENSE_SMEM);

    int n4           = N * (D / 4);
    int spmm_blocks  = (int)(((long long)E * 16 + 255) / 256);
    int dense_blocks = (N + DB_ROWS - 1) / DB_ROWS;

    // Layer 1
    zero_kernel<<<2048, 256>>>((float4*)nbr, n4);
    spmm_kernel<<<spmm_blocks, 256>>>(rows, cols, vals, emb, nbr, E);
    dense_kernel<<<dense_blocks, DB_THREADS, DENSE_SMEM>>>(emb, nbr, W1, b1, h1, N);

    // Layer 2
    zero_kernel<<<2048, 256>>>((float4*)nbr, n4);
    spmm_kernel<<<spmm_blocks, 256>>>(rows, cols, vals, h1, nbr, E);
    dense_kernel<<<dense_blocks, DB_THREADS, DENSE_SMEM>>>(h1, nbr, W2, b2, out, N);
}